// round 14
// baseline (speedup 1.0000x reference)
#include <cuda_runtime.h>
#include <cuda_fp16.h>
#include <math.h>
#include <stdint.h>

// Problem constants
#define N_TOK 16384
#define DIM   1024
#define HID   4096
#define NEXP  8
#define NPAIR (2*N_TOK)
#define PADR  128

// GEMM tiling: CTA 128x256x64, warp 64x64, 8 warps, 3-stage cp.async ring
#define BM 128
#define BN 256
#define BK 64
#define NSTAGE 3
#define AST 72    // A smem row stride (elems): 144B, 144%128=16 -> conflict-free
#define BST 264   // B smem row stride (elems): 528B, 528%128=16 -> conflict-free

#define ABYTES (BM*AST*2)                 // 18432
#define BBYTES (BK*BST*2)                 // 33792
#define STB    (ABYTES + BBYTES)          // 52224 per stage
#define SMEM_G1 (512 + NSTAGE*STB)        // tokS + stages = 157184
#define SMEM_G2 (NSTAGE*STB)              // 156672

// ---------------- device scratch (static: no runtime allocation) ----------------
__device__ __half g_xh [(size_t)N_TOK*DIM];
__device__ __half g_W1h[(size_t)NEXP*DIM*HID];
__device__ __half g_W2h[(size_t)NEXP*HID*DIM];
__device__ __half g_H1 [((size_t)NPAIR+PADR)*HID];
__device__ float  g_S  [((size_t)NPAIR+PADR)*DIM];
__device__ int   g_cnt[NEXP];
__device__ int   g_basearr[NEXP];
__device__ int   g_run[NEXP];
__device__ int   g_tok [NPAIR+PADR];
__device__ float g_gate[NPAIR+PADR];
__device__ int   g_prow[NPAIR];
__device__ int   g_tki [NPAIR];
__device__ float g_tkp [NPAIR];

// ---------------- PTX helpers ----------------
static __device__ __forceinline__ uint32_t smem_u32(const void* p){
    return (uint32_t)__cvta_generic_to_shared(p);
}
static __device__ __forceinline__ void cp16(void* s, const void* g){
    asm volatile("cp.async.cg.shared.global [%0],[%1],16;\n" :: "r"(smem_u32(s)), "l"(g));
}
#define CP_COMMIT() asm volatile("cp.async.commit_group;\n")
#define CP_WAIT(n)  asm volatile("cp.async.wait_group %0;\n"::"n"(n))

static __device__ __forceinline__ void ldm4(uint32_t &r0,uint32_t &r1,uint32_t &r2,uint32_t &r3,uint32_t a){
    asm volatile("ldmatrix.sync.aligned.m8n8.x4.shared.b16 {%0,%1,%2,%3},[%4];\n"
                 : "=r"(r0),"=r"(r1),"=r"(r2),"=r"(r3) : "r"(a));
}
static __device__ __forceinline__ void ldm4t(uint32_t &r0,uint32_t &r1,uint32_t &r2,uint32_t &r3,uint32_t a){
    asm volatile("ldmatrix.sync.aligned.m8n8.x4.trans.shared.b16 {%0,%1,%2,%3},[%4];\n"
                 : "=r"(r0),"=r"(r1),"=r"(r2),"=r"(r3) : "r"(a));
}
static __device__ __forceinline__ void mma16816(float* c,
        uint32_t a0,uint32_t a1,uint32_t a2,uint32_t a3, uint32_t b0,uint32_t b1){
    asm volatile("mma.sync.aligned.m16n8k16.row.col.f32.f16.f16.f32 "
        "{%0,%1,%2,%3},{%4,%5,%6,%7},{%8,%9},{%0,%1,%2,%3};\n"
        : "+f"(c[0]),"+f"(c[1]),"+f"(c[2]),"+f"(c[3])
        : "r"(a0),"r"(a1),"r"(a2),"r"(a3),"r"(b0),"r"(b1));
}
static __device__ __forceinline__ float gelu_f(float x){
    return 0.5f*x*(1.0f + erff(x*0.70710678118654752f));
}

// ---------------- conversion kernels (vectorized) ----------------
__global__ void cvtx_kernel(const float4* __restrict__ src, __half* __restrict__ dst, int n4){
    int i = blockIdx.x*blockDim.x + threadIdx.x;
    if (blockIdx.x == 0 && threadIdx.x < NEXP) g_cnt[threadIdx.x] = 0;
    if (i < n4){
        float4 v = src[i];
        __half2 h0 = __floats2half2_rn(v.x, v.y);
        __half2 h1 = __floats2half2_rn(v.z, v.w);
        ((uint2*)dst)[i] = make_uint2(*(uint32_t*)&h0, *(uint32_t*)&h1);
    }
}
__global__ void cvtW_kernel(const float4* __restrict__ s1, __half* __restrict__ d1,
                            const float4* __restrict__ s2, __half* __restrict__ d2, int n4){
    int i = blockIdx.x*blockDim.x + threadIdx.x;
    const float4* s = s1; __half* d = d1;
    if (i >= n4){ s = s2; d = d2; i -= n4; }
    float4 v = s[i];
    __half2 h0 = __floats2half2_rn(v.x, v.y);
    __half2 h1 = __floats2half2_rn(v.z, v.w);
    ((uint2*)d)[i] = make_uint2(*(uint32_t*)&h0, *(uint32_t*)&h1);
}

// ---------------- router / scan / pairs ----------------
__global__ __launch_bounds__(256) void router_kernel(
        const float* __restrict__ x, const float* __restrict__ grad,
        const float* __restrict__ rW, const float* __restrict__ rb,
        float* __restrict__ probs){
    __shared__ float sW[DIM*NEXP];
    for (int i = threadIdx.x; i < DIM*NEXP; i += 256) sW[i] = rW[i];
    __syncthreads();
    int warp = threadIdx.x >> 5, lane = threadIdx.x & 31;
    int n = blockIdx.x*8 + warp;
    const float* xr = x + (size_t)n*DIM;
    float a[NEXP];
    #pragma unroll
    for (int e=0;e<NEXP;e++) a[e]=0.f;
    for (int d=lane; d<DIM; d+=32){
        float xv = xr[d];
        #pragma unroll
        for (int e=0;e<NEXP;e++) a[e] += xv * sW[d*NEXP+e];
    }
    #pragma unroll
    for (int off=16; off; off>>=1){
        #pragma unroll
        for (int e=0;e<NEXP;e++) a[e] += __shfl_xor_sync(0xffffffffu, a[e], off);
    }
    float g = grad[n];
    #pragma unroll
    for (int e=0;e<NEXP;e++) a[e] += g*rW[DIM*NEXP+e] + rb[e];
    float mx = a[0];
    #pragma unroll
    for (int e=1;e<NEXP;e++) mx = fmaxf(mx, a[e]);
    float s = 0.f;
    #pragma unroll
    for (int e=0;e<NEXP;e++){ a[e] = expf(a[e]-mx); s += a[e]; }
    float inv = 1.f/s;
    #pragma unroll
    for (int e=0;e<NEXP;e++) a[e] *= inv;
    if (lane < NEXP) probs[(size_t)n*NEXP + lane] = a[lane];
    if (lane == 0){
        int i0 = 0; float p0 = a[0];
        #pragma unroll
        for (int e=1;e<NEXP;e++) if (a[e] > p0){ p0=a[e]; i0=e; }
        int i1 = -1; float p1 = -1.f;
        #pragma unroll
        for (int e=0;e<NEXP;e++) if (e!=i0 && a[e] > p1){ p1=a[e]; i1=e; }
        g_tki[2*n]   = i0; g_tkp[2*n]   = p0;
        g_tki[2*n+1] = i1; g_tkp[2*n+1] = p1;
        atomicAdd(&g_cnt[i0],1);
        atomicAdd(&g_cnt[i1],1);
    }
}

__global__ void scan_kernel(){
    if (threadIdx.x==0){
        int b=0;
        for (int e=0;e<NEXP;e++){ g_basearr[e]=b; g_run[e]=b; b+=g_cnt[e]; }
    }
}

__global__ void pairs_kernel(){
    int p = blockIdx.x*blockDim.x + threadIdx.x;
    if (p >= NPAIR) return;
    int e = g_tki[p];
    int slot = atomicAdd(&g_run[e], 1);
    g_tok[slot]  = p >> 1;
    g_gate[slot] = g_tkp[p];
    g_prow[p]    = slot;
}

// ---------------- GEMM 1: H1[slot,:] = gelu(x[tok[slot]] @ W1[e] + b1[e]) ----------------
__global__ __launch_bounds__(256,1) void gemm1_kernel(const float* __restrict__ b1){
    extern __shared__ char smem_raw[];
    int*    tokS = (int*)smem_raw;
    char*   stg  = smem_raw + 512;

    int e   = blockIdx.z;
    int cnt = g_cnt[e];
    int m0  = blockIdx.y*BM;
    if (m0 >= cnt) return;
    int n0    = blockIdx.x*BN;
    int baseE = g_basearr[e];

    int tid = threadIdx.x;
    if (tid < BM) tokS[tid] = g_tok[baseE + m0 + tid];   // padded array: safe past cnt
    __syncthreads();

    const __half* Bg = g_W1h + (size_t)e*DIM*HID;

    int wid = tid>>5, lane = tid&31;
    int wr = (wid>>2)*64, wc = (wid&3)*64;
    float acc[4][8][4];
    #pragma unroll
    for (int i=0;i<4;i++)
        #pragma unroll
        for (int j=0;j<8;j++)
            #pragma unroll
            for (int q=0;q<4;q++) acc[i][j][q]=0.f;

    auto loadStage = [&](int st, int k0){
        __half* Ad = (__half*)(stg + st*STB);
        __half* Bd = (__half*)(stg + st*STB + ABYTES);
        #pragma unroll
        for (int i=0;i<4;i++){                      // A: 1024 chunks
            int c = tid + i*256; int r = c>>3, s8 = (c&7)*8;
            cp16(&Ad[r*AST+s8], g_xh + (size_t)tokS[r]*DIM + k0 + s8);
        }
        #pragma unroll
        for (int i=0;i<8;i++){                      // B: 2048 chunks
            int c = tid + i*256; int r = c>>5, s8 = (c&31)*8;
            cp16(&Bd[r*BST+s8], Bg + (size_t)(k0+r)*HID + n0 + s8);
        }
    };

    loadStage(0, 0);   CP_COMMIT();
    loadStage(1, BK);  CP_COMMIT();

    const int KT = DIM/BK;   // 16
    for (int kt=0; kt<KT; kt++){
        if (kt < KT-1) { CP_WAIT(1); } else { CP_WAIT(0); }
        __syncthreads();
        if (kt+2 < KT){ loadStage((kt+2)%NSTAGE, (kt+2)*BK); CP_COMMIT(); }

        int st = kt % NSTAGE;
        const __half* Ast = (const __half*)(stg + st*STB);
        const __half* Bst = (const __half*)(stg + st*STB + ABYTES);
        #pragma unroll
        for (int kk=0; kk<BK; kk+=16){
            uint32_t a[4][4];
            #pragma unroll
            for (int mi=0;mi<4;mi++){
                int r  = wr + mi*16 + (lane&15);
                int cb = kk + (lane>>4)*8;
                ldm4(a[mi][0],a[mi][1],a[mi][2],a[mi][3], smem_u32(&Ast[r*AST+cb]));
            }
            uint32_t b[4][4];
            #pragma unroll
            for (int nj=0;nj<4;nj++){
                int r  = kk + (lane&15);
                int cb = wc + nj*16 + (lane>>4)*8;
                ldm4t(b[nj][0],b[nj][1],b[nj][2],b[nj][3], smem_u32(&Bst[r*BST+cb]));
            }
            #pragma unroll
            for (int mi=0;mi<4;mi++)
                #pragma unroll
                for (int ni=0;ni<8;ni++)
                    mma16816(acc[mi][ni], a[mi][0],a[mi][1],a[mi][2],a[mi][3],
                             b[ni>>1][(ni&1)*2], b[ni>>1][(ni&1)*2+1]);
        }
        __syncthreads();
    }

    const float* b1e = b1 + (size_t)e*HID;
    #pragma unroll
    for (int mi=0;mi<4;mi++){
        #pragma unroll
        for (int i=0;i<2;i++){
            int r = wr + mi*16 + (lane>>2) + i*8;
            int m = m0 + r;
            if (m < cnt){
                __half* Hrow = g_H1 + (size_t)(baseE+m)*HID;
                #pragma unroll
                for (int ni=0;ni<8;ni++){
                    int cb = n0 + wc + ni*8 + (lane&3)*2;
                    float v0 = gelu_f(acc[mi][ni][i*2+0] + b1e[cb]);
                    float v1 = gelu_f(acc[mi][ni][i*2+1] + b1e[cb+1]);
                    *((__half2*)(Hrow + cb)) = __floats2half2_rn(v0, v1);
                }
            }
        }
    }
}

// ---------------- GEMM 2: S[slot,:] = gate[slot] * (H1[slot] @ W2[e] + b2[e]) ----------------
__global__ __launch_bounds__(256,1) void gemm2_kernel(const float* __restrict__ b2){
    extern __shared__ char smem_raw[];
    char* stg = smem_raw;

    int e   = blockIdx.z;
    int cnt = g_cnt[e];
    int m0  = blockIdx.y*BM;
    if (m0 >= cnt) return;
    int n0    = blockIdx.x*BN;
    int baseE = g_basearr[e];

    int tid = threadIdx.x;
    const __half* Ag = g_H1  + (size_t)(baseE+m0)*HID;
    const __half* Bg = g_W2h + (size_t)e*HID*DIM;

    int wid = tid>>5, lane = tid&31;
    int wr = (wid>>2)*64, wc = (wid&3)*64;
    float acc[4][8][4];
    #pragma unroll
    for (int i=0;i<4;i++)
        #pragma unroll
        for (int j=0;j<8;j++)
            #pragma unroll
            for (int q=0;q<4;q++) acc[i][j][q]=0.f;

    auto loadStage = [&](int st, int k0){
        __half* Ad = (__half*)(stg + st*STB);
        __half* Bd = (__half*)(stg + st*STB + ABYTES);
        #pragma unroll
        for (int i=0;i<4;i++){
            int c = tid + i*256; int r = c>>3, s8 = (c&7)*8;
            cp16(&Ad[r*AST+s8], Ag + (size_t)r*HID + k0 + s8);
        }
        #pragma unroll
        for (int i=0;i<8;i++){
            int c = tid + i*256; int r = c>>5, s8 = (c&31)*8;
            cp16(&Bd[r*BST+s8], Bg + (size_t)(k0+r)*DIM + n0 + s8);
        }
    };

    loadStage(0, 0);   CP_COMMIT();
    loadStage(1, BK);  CP_COMMIT();

    const int KT = HID/BK;   // 64
    for (int kt=0; kt<KT; kt++){
        if (kt < KT-1) { CP_WAIT(1); } else { CP_WAIT(0); }
        __syncthreads();
        if (kt+2 < KT){ loadStage((kt+2)%NSTAGE, (kt+2)*BK); CP_COMMIT(); }

        int st = kt % NSTAGE;
        const __half* Ast = (const __half*)(stg + st*STB);
        const __half* Bst = (const __half*)(stg + st*STB + ABYTES);
        #pragma unroll
        for (int kk=0; kk<BK; kk+=16){
            uint32_t a[4][4];
            #pragma unroll
            for (int mi=0;mi<4;mi++){
                int r  = wr + mi*16 + (lane&15);
                int cb = kk + (lane>>4)*8;
                ldm4(a[mi][0],a[mi][1],a[mi][2],a[mi][3], smem_u32(&Ast[r*AST+cb]));
            }
            uint32_t b[4][4];
            #pragma unroll
            for (int nj=0;nj<4;nj++){
                int r  = kk + (lane&15);
                int cb = wc + nj*16 + (lane>>4)*8;
                ldm4t(b[nj][0],b[nj][1],b[nj][2],b[nj][3], smem_u32(&Bst[r*BST+cb]));
            }
            #pragma unroll
            for (int mi=0;mi<4;mi++)
                #pragma unroll
                for (int ni=0;ni<8;ni++)
                    mma16816(acc[mi][ni], a[mi][0],a[mi][1],a[mi][2],a[mi][3],
                             b[ni>>1][(ni&1)*2], b[ni>>1][(ni&1)*2+1]);
        }
        __syncthreads();
    }

    const float* b2e = b2 + (size_t)e*DIM;
    #pragma unroll
    for (int mi=0;mi<4;mi++){
        #pragma unroll
        for (int i=0;i<2;i++){
            int r = wr + mi*16 + (lane>>2) + i*8;
            int m = m0 + r;
            if (m < cnt){
                int slot = baseE + m;
                float gate = g_gate[slot];
                float* Srow = g_S + (size_t)slot*DIM;
                #pragma unroll
                for (int ni=0;ni<8;ni++){
                    int cb = n0 + wc + ni*8 + (lane&3)*2;
                    float v0 = gate*(acc[mi][ni][i*2+0] + b2e[cb]);
                    float v1 = gate*(acc[mi][ni][i*2+1] + b2e[cb+1]);
                    *((float2*)(Srow + cb)) = make_float2(v0, v1);
                }
            }
        }
    }
}

// ---------------- combine: out[n] = S[prow[2n]] + S[prow[2n+1]] ----------------
__global__ void combine_kernel(float* __restrict__ out){
    int t = blockIdx.x*blockDim.x + threadIdx.x;   // over N_TOK*DIM/4
    if (t >= N_TOK*(DIM/4)) return;
    int n  = t >> 8;        // DIM/4 = 256
    int c4 = t & 255;
    int p0 = g_prow[2*n], p1 = g_prow[2*n+1];
    const float4* s0 = (const float4*)(g_S + (size_t)p0*DIM);
    const float4* s1 = (const float4*)(g_S + (size_t)p1*DIM);
    float4 v0 = s0[c4], v1 = s1[c4];
    float4 r;
    r.x = v0.x+v1.x; r.y = v0.y+v1.y; r.z = v0.z+v1.z; r.w = v0.w+v1.w;
    ((float4*)out)[t] = r;
}

// ---------------- launch ----------------
extern "C" void kernel_launch(void* const* d_in, const int* in_sizes, int n_in,
                              void* d_out, int out_size){
    (void)in_sizes; (void)n_in; (void)out_size;
    const float* x    = (const float*)d_in[0];
    const float* grad = (const float*)d_in[1];
    const float* rW   = (const float*)d_in[2];
    const float* rb   = (const float*)d_in[3];
    const float* W1   = (const float*)d_in[4];
    const float* b1   = (const float*)d_in[5];
    const float* W2   = (const float*)d_in[6];
    const float* b2   = (const float*)d_in[7];
    float* out   = (float*)d_out;
    float* probs = out + (size_t)N_TOK*DIM;

    void *p_xh=nullptr, *p_w1=nullptr, *p_w2=nullptr;
    cudaGetSymbolAddress(&p_xh, g_xh);
    cudaGetSymbolAddress(&p_w1, g_W1h);
    cudaGetSymbolAddress(&p_w2, g_W2h);

    cudaFuncSetAttribute(gemm1_kernel, cudaFuncAttributeMaxDynamicSharedMemorySize, SMEM_G1);
    cudaFuncSetAttribute(gemm2_kernel, cudaFuncAttributeMaxDynamicSharedMemorySize, SMEM_G2);

    // 1: x convert (+counter reset)
    {
        int n4 = N_TOK*DIM/4;
        cvtx_kernel<<<n4/256,256>>>((const float4*)x, (__half*)p_xh, n4);
    }
    // 2: W1+W2 convert
    {
        int n4 = NEXP*DIM*HID/4;
        cvtW_kernel<<<2*n4/256,256>>>((const float4*)W1, (__half*)p_w1,
                                      (const float4*)W2, (__half*)p_w2, n4);
    }
    // 3-5: routing
    router_kernel<<<N_TOK/8,256>>>(x, grad, rW, rb, probs);
    scan_kernel<<<1,32>>>();
    pairs_kernel<<<NPAIR/256,256>>>();
    // 6-7: grouped GEMMs (CTA tile 128x256x64)
    gemm1_kernel<<<dim3(HID/BN, N_TOK/BM, NEXP),256,SMEM_G1>>>(b1);
    gemm2_kernel<<<dim3(DIM/BN, N_TOK/BM, NEXP),256,SMEM_G2>>>(b2);
    // 8: combine
    combine_kernel<<<(N_TOK*(DIM/4)+255)/256,256>>>(out);
}

// round 15
// speedup vs baseline: 1.1300x; 1.1300x over previous
#include <cuda_runtime.h>
#include <cuda_fp16.h>
#include <math.h>
#include <stdint.h>

// Problem constants
#define N_TOK 16384
#define DIM   1024
#define HID   4096
#define NEXP  8
#define NPAIR (2*N_TOK)
#define PADR  128

// GEMM tiling: CTA 128x128x64, warp 64x32, 8 warps, 3-stage cp.async ring, 2 CTA/SM
#define BM 128
#define BN 128
#define BK 64
#define NSTAGE 3
#define AST 72    // A smem row stride (elems): 144B (144%128=16) -> conflict-free
#define BST 136   // B smem row stride (elems): 272B (272%128=16) -> conflict-free

#define ABYTES (BM*AST*2)                 // 18432
#define BBYTES (BK*BST*2)                 // 17408
#define STB    (ABYTES + BBYTES)          // 35840 per stage
#define SMEM_G1 (512 + NSTAGE*STB)        // tokS + stages = 108032
#define SMEM_G2 (NSTAGE*STB)              // 107520

// ---------------- device scratch (static: no runtime allocation) ----------------
__device__ __half g_xh [(size_t)N_TOK*DIM];
__device__ __half g_W1h[(size_t)NEXP*DIM*HID];
__device__ __half g_W2h[(size_t)NEXP*HID*DIM];
__device__ __half g_H1 [((size_t)NPAIR+PADR)*HID];
__device__ float  g_S  [((size_t)NPAIR+PADR)*DIM];
__device__ int   g_cnt[NEXP];
__device__ int   g_basearr[NEXP];
__device__ int   g_run[NEXP];
__device__ int   g_tok [NPAIR+PADR];
__device__ float g_gate[NPAIR+PADR];
__device__ int   g_prow[NPAIR];
__device__ int   g_tki [NPAIR];
__device__ float g_tkp [NPAIR];

// ---------------- PTX helpers ----------------
static __device__ __forceinline__ uint32_t smem_u32(const void* p){
    return (uint32_t)__cvta_generic_to_shared(p);
}
static __device__ __forceinline__ void cp16(void* s, const void* g){
    asm volatile("cp.async.cg.shared.global [%0],[%1],16;\n" :: "r"(smem_u32(s)), "l"(g));
}
#define CP_COMMIT() asm volatile("cp.async.commit_group;\n")
#define CP_WAIT(n)  asm volatile("cp.async.wait_group %0;\n"::"n"(n))

static __device__ __forceinline__ void ldm4(uint32_t &r0,uint32_t &r1,uint32_t &r2,uint32_t &r3,uint32_t a){
    asm volatile("ldmatrix.sync.aligned.m8n8.x4.shared.b16 {%0,%1,%2,%3},[%4];\n"
                 : "=r"(r0),"=r"(r1),"=r"(r2),"=r"(r3) : "r"(a));
}
static __device__ __forceinline__ void ldm4t(uint32_t &r0,uint32_t &r1,uint32_t &r2,uint32_t &r3,uint32_t a){
    asm volatile("ldmatrix.sync.aligned.m8n8.x4.trans.shared.b16 {%0,%1,%2,%3},[%4];\n"
                 : "=r"(r0),"=r"(r1),"=r"(r2),"=r"(r3) : "r"(a));
}
static __device__ __forceinline__ void mma16816(float* c,
        uint32_t a0,uint32_t a1,uint32_t a2,uint32_t a3, uint32_t b0,uint32_t b1){
    asm volatile("mma.sync.aligned.m16n8k16.row.col.f32.f16.f16.f32 "
        "{%0,%1,%2,%3},{%4,%5,%6,%7},{%8,%9},{%0,%1,%2,%3};\n"
        : "+f"(c[0]),"+f"(c[1]),"+f"(c[2]),"+f"(c[3])
        : "r"(a0),"r"(a1),"r"(a2),"r"(a3),"r"(b0),"r"(b1));
}
static __device__ __forceinline__ float gelu_f(float x){
    return 0.5f*x*(1.0f + erff(x*0.70710678118654752f));
}

// ---------------- conversion kernels (vectorized) ----------------
__global__ void cvtx_kernel(const float4* __restrict__ src, __half* __restrict__ dst, int n4){
    int i = blockIdx.x*blockDim.x + threadIdx.x;
    if (blockIdx.x == 0 && threadIdx.x < NEXP) g_cnt[threadIdx.x] = 0;
    if (i < n4){
        float4 v = src[i];
        __half2 h0 = __floats2half2_rn(v.x, v.y);
        __half2 h1 = __floats2half2_rn(v.z, v.w);
        ((uint2*)dst)[i] = make_uint2(*(uint32_t*)&h0, *(uint32_t*)&h1);
    }
}
__global__ void cvtW_kernel(const float4* __restrict__ s1, __half* __restrict__ d1,
                            const float4* __restrict__ s2, __half* __restrict__ d2, int n4){
    int i = blockIdx.x*blockDim.x + threadIdx.x;
    const float4* s = s1; __half* d = d1;
    if (i >= n4){ s = s2; d = d2; i -= n4; }
    float4 v = s[i];
    __half2 h0 = __floats2half2_rn(v.x, v.y);
    __half2 h1 = __floats2half2_rn(v.z, v.w);
    ((uint2*)d)[i] = make_uint2(*(uint32_t*)&h0, *(uint32_t*)&h1);
}

// ---------------- router / scan / pairs ----------------
__global__ __launch_bounds__(256) void router_kernel(
        const float* __restrict__ x, const float* __restrict__ grad,
        const float* __restrict__ rW, const float* __restrict__ rb,
        float* __restrict__ probs){
    __shared__ float sW[DIM*NEXP];
    for (int i = threadIdx.x; i < DIM*NEXP; i += 256) sW[i] = rW[i];
    __syncthreads();
    int warp = threadIdx.x >> 5, lane = threadIdx.x & 31;
    int n = blockIdx.x*8 + warp;
    const float* xr = x + (size_t)n*DIM;
    float a[NEXP];
    #pragma unroll
    for (int e=0;e<NEXP;e++) a[e]=0.f;
    for (int d=lane; d<DIM; d+=32){
        float xv = xr[d];
        #pragma unroll
        for (int e=0;e<NEXP;e++) a[e] += xv * sW[d*NEXP+e];
    }
    #pragma unroll
    for (int off=16; off; off>>=1){
        #pragma unroll
        for (int e=0;e<NEXP;e++) a[e] += __shfl_xor_sync(0xffffffffu, a[e], off);
    }
    float g = grad[n];
    #pragma unroll
    for (int e=0;e<NEXP;e++) a[e] += g*rW[DIM*NEXP+e] + rb[e];
    float mx = a[0];
    #pragma unroll
    for (int e=1;e<NEXP;e++) mx = fmaxf(mx, a[e]);
    float s = 0.f;
    #pragma unroll
    for (int e=0;e<NEXP;e++){ a[e] = expf(a[e]-mx); s += a[e]; }
    float inv = 1.f/s;
    #pragma unroll
    for (int e=0;e<NEXP;e++) a[e] *= inv;
    if (lane < NEXP) probs[(size_t)n*NEXP + lane] = a[lane];
    if (lane == 0){
        int i0 = 0; float p0 = a[0];
        #pragma unroll
        for (int e=1;e<NEXP;e++) if (a[e] > p0){ p0=a[e]; i0=e; }
        int i1 = -1; float p1 = -1.f;
        #pragma unroll
        for (int e=0;e<NEXP;e++) if (e!=i0 && a[e] > p1){ p1=a[e]; i1=e; }
        g_tki[2*n]   = i0; g_tkp[2*n]   = p0;
        g_tki[2*n+1] = i1; g_tkp[2*n+1] = p1;
        atomicAdd(&g_cnt[i0],1);
        atomicAdd(&g_cnt[i1],1);
    }
}

__global__ void scan_kernel(){
    if (threadIdx.x==0){
        int b=0;
        for (int e=0;e<NEXP;e++){ g_basearr[e]=b; g_run[e]=b; b+=g_cnt[e]; }
    }
}

__global__ void pairs_kernel(){
    int p = blockIdx.x*blockDim.x + threadIdx.x;
    if (p >= NPAIR) return;
    int e = g_tki[p];
    int slot = atomicAdd(&g_run[e], 1);
    g_tok[slot]  = p >> 1;
    g_gate[slot] = g_tkp[p];
    g_prow[p]    = slot;
}

// ---------------- GEMM 1: H1[slot,:] = gelu(x[tok[slot]] @ W1[e] + b1[e]) ----------------
__global__ __launch_bounds__(256,2) void gemm1_kernel(const float* __restrict__ b1){
    extern __shared__ char smem_raw[];
    int*    tokS = (int*)smem_raw;
    char*   stg  = smem_raw + 512;

    int e   = blockIdx.z;
    int cnt = g_cnt[e];
    int m0  = blockIdx.y*BM;
    if (m0 >= cnt) return;
    int n0    = blockIdx.x*BN;
    int baseE = g_basearr[e];

    int tid = threadIdx.x;
    if (tid < BM) tokS[tid] = g_tok[baseE + m0 + tid];   // padded array: safe past cnt
    __syncthreads();

    const __half* Bg = g_W1h + (size_t)e*DIM*HID;

    int wid = tid>>5, lane = tid&31;
    int wr = (wid>>2)*64, wc = (wid&3)*32;
    float acc[4][4][4];
    #pragma unroll
    for (int i=0;i<4;i++)
        #pragma unroll
        for (int j=0;j<4;j++)
            #pragma unroll
            for (int q=0;q<4;q++) acc[i][j][q]=0.f;

    auto loadStage = [&](int st, int k0){
        __half* Ad = (__half*)(stg + st*STB);
        __half* Bd = (__half*)(stg + st*STB + ABYTES);
        #pragma unroll
        for (int i=0;i<4;i++){                    // A: 128 rows x 64 cols = 1024 chunks
            int c = tid + i*256; int r = c>>3, s8 = (c&7)*8;
            cp16(&Ad[r*AST+s8], g_xh + (size_t)tokS[r]*DIM + k0 + s8);
        }
        #pragma unroll
        for (int i=0;i<4;i++){                    // B: 64 rows x 128 cols = 1024 chunks
            int c = tid + i*256; int r = c>>4, s8 = (c&15)*8;
            cp16(&Bd[r*BST+s8], Bg + (size_t)(k0+r)*HID + n0 + s8);
        }
    };

    loadStage(0, 0);   CP_COMMIT();
    loadStage(1, BK);  CP_COMMIT();

    const int KT = DIM/BK;   // 16
    for (int kt=0; kt<KT; kt++){
        if (kt < KT-1) { CP_WAIT(1); } else { CP_WAIT(0); }
        __syncthreads();
        if (kt+2 < KT){ loadStage((kt+2)%NSTAGE, (kt+2)*BK); CP_COMMIT(); }

        int st = kt % NSTAGE;
        const __half* Ast = (const __half*)(stg + st*STB);
        const __half* Bst = (const __half*)(stg + st*STB + ABYTES);
        #pragma unroll
        for (int kk=0; kk<BK; kk+=16){
            uint32_t a[4][4];
            #pragma unroll
            for (int mi=0;mi<4;mi++){
                int r  = wr + mi*16 + (lane&15);
                int cb = kk + (lane>>4)*8;
                ldm4(a[mi][0],a[mi][1],a[mi][2],a[mi][3], smem_u32(&Ast[r*AST+cb]));
            }
            uint32_t b[2][4];
            #pragma unroll
            for (int nj=0;nj<2;nj++){
                int r  = kk + (lane&15);
                int cb = wc + nj*16 + (lane>>4)*8;
                ldm4t(b[nj][0],b[nj][1],b[nj][2],b[nj][3], smem_u32(&Bst[r*BST+cb]));
            }
            #pragma unroll
            for (int mi=0;mi<4;mi++)
                #pragma unroll
                for (int ni=0;ni<4;ni++)
                    mma16816(acc[mi][ni], a[mi][0],a[mi][1],a[mi][2],a[mi][3],
                             b[ni>>1][(ni&1)*2], b[ni>>1][(ni&1)*2+1]);
        }
        __syncthreads();
    }

    const float* b1e = b1 + (size_t)e*HID;
    #pragma unroll
    for (int mi=0;mi<4;mi++){
        #pragma unroll
        for (int i=0;i<2;i++){
            int r = wr + mi*16 + (lane>>2) + i*8;
            int m = m0 + r;
            if (m < cnt){
                __half* Hrow = g_H1 + (size_t)(baseE+m)*HID;
                #pragma unroll
                for (int ni=0;ni<4;ni++){
                    int cb = n0 + wc + ni*8 + (lane&3)*2;
                    float v0 = gelu_f(acc[mi][ni][i*2+0] + b1e[cb]);
                    float v1 = gelu_f(acc[mi][ni][i*2+1] + b1e[cb+1]);
                    *((__half2*)(Hrow + cb)) = __floats2half2_rn(v0, v1);
                }
            }
        }
    }
}

// ---------------- GEMM 2: S[slot,:] = gate[slot] * (H1[slot] @ W2[e] + b2[e]) ----------------
__global__ __launch_bounds__(256,2) void gemm2_kernel(const float* __restrict__ b2){
    extern __shared__ char smem_raw[];
    char* stg = smem_raw;

    int e   = blockIdx.z;
    int cnt = g_cnt[e];
    int m0  = blockIdx.y*BM;
    if (m0 >= cnt) return;
    int n0    = blockIdx.x*BN;
    int baseE = g_basearr[e];

    int tid = threadIdx.x;
    const __half* Ag = g_H1  + (size_t)(baseE+m0)*HID;
    const __half* Bg = g_W2h + (size_t)e*HID*DIM;

    int wid = tid>>5, lane = tid&31;
    int wr = (wid>>2)*64, wc = (wid&3)*32;
    float acc[4][4][4];
    #pragma unroll
    for (int i=0;i<4;i++)
        #pragma unroll
        for (int j=0;j<4;j++)
            #pragma unroll
            for (int q=0;q<4;q++) acc[i][j][q]=0.f;

    auto loadStage = [&](int st, int k0){
        __half* Ad = (__half*)(stg + st*STB);
        __half* Bd = (__half*)(stg + st*STB + ABYTES);
        #pragma unroll
        for (int i=0;i<4;i++){
            int c = tid + i*256; int r = c>>3, s8 = (c&7)*8;
            cp16(&Ad[r*AST+s8], Ag + (size_t)r*HID + k0 + s8);
        }
        #pragma unroll
        for (int i=0;i<4;i++){
            int c = tid + i*256; int r = c>>4, s8 = (c&15)*8;
            cp16(&Bd[r*BST+s8], Bg + (size_t)(k0+r)*DIM + n0 + s8);
        }
    };

    loadStage(0, 0);   CP_COMMIT();
    loadStage(1, BK);  CP_COMMIT();

    const int KT = HID/BK;   // 64
    for (int kt=0; kt<KT; kt++){
        if (kt < KT-1) { CP_WAIT(1); } else { CP_WAIT(0); }
        __syncthreads();
        if (kt+2 < KT){ loadStage((kt+2)%NSTAGE, (kt+2)*BK); CP_COMMIT(); }

        int st = kt % NSTAGE;
        const __half* Ast = (const __half*)(stg + st*STB);
        const __half* Bst = (const __half*)(stg + st*STB + ABYTES);
        #pragma unroll
        for (int kk=0; kk<BK; kk+=16){
            uint32_t a[4][4];
            #pragma unroll
            for (int mi=0;mi<4;mi++){
                int r  = wr + mi*16 + (lane&15);
                int cb = kk + (lane>>4)*8;
                ldm4(a[mi][0],a[mi][1],a[mi][2],a[mi][3], smem_u32(&Ast[r*AST+cb]));
            }
            uint32_t b[2][4];
            #pragma unroll
            for (int nj=0;nj<2;nj++){
                int r  = kk + (lane&15);
                int cb = wc + nj*16 + (lane>>4)*8;
                ldm4t(b[nj][0],b[nj][1],b[nj][2],b[nj][3], smem_u32(&Bst[r*BST+cb]));
            }
            #pragma unroll
            for (int mi=0;mi<4;mi++)
                #pragma unroll
                for (int ni=0;ni<4;ni++)
                    mma16816(acc[mi][ni], a[mi][0],a[mi][1],a[mi][2],a[mi][3],
                             b[ni>>1][(ni&1)*2], b[ni>>1][(ni&1)*2+1]);
        }
        __syncthreads();
    }

    const float* b2e = b2 + (size_t)e*DIM;
    #pragma unroll
    for (int mi=0;mi<4;mi++){
        #pragma unroll
        for (int i=0;i<2;i++){
            int r = wr + mi*16 + (lane>>2) + i*8;
            int m = m0 + r;
            if (m < cnt){
                int slot = baseE + m;
                float gate = g_gate[slot];
                float* Srow = g_S + (size_t)slot*DIM;
                #pragma unroll
                for (int ni=0;ni<4;ni++){
                    int cb = n0 + wc + ni*8 + (lane&3)*2;
                    float v0 = gate*(acc[mi][ni][i*2+0] + b2e[cb]);
                    float v1 = gate*(acc[mi][ni][i*2+1] + b2e[cb+1]);
                    *((float2*)(Srow + cb)) = make_float2(v0, v1);
                }
            }
        }
    }
}

// ---------------- combine: out[n] = S[prow[2n]] + S[prow[2n+1]] ----------------
__global__ void combine_kernel(float* __restrict__ out){
    int t = blockIdx.x*blockDim.x + threadIdx.x;   // over N_TOK*DIM/4
    if (t >= N_TOK*(DIM/4)) return;
    int n  = t >> 8;        // DIM/4 = 256
    int c4 = t & 255;
    int p0 = g_prow[2*n], p1 = g_prow[2*n+1];
    const float4* s0 = (const float4*)(g_S + (size_t)p0*DIM);
    const float4* s1 = (const float4*)(g_S + (size_t)p1*DIM);
    float4 v0 = s0[c4], v1 = s1[c4];
    float4 r;
    r.x = v0.x+v1.x; r.y = v0.y+v1.y; r.z = v0.z+v1.z; r.w = v0.w+v1.w;
    ((float4*)out)[t] = r;
}

// ---------------- launch ----------------
extern "C" void kernel_launch(void* const* d_in, const int* in_sizes, int n_in,
                              void* d_out, int out_size){
    (void)in_sizes; (void)n_in; (void)out_size;
    const float* x    = (const float*)d_in[0];
    const float* grad = (const float*)d_in[1];
    const float* rW   = (const float*)d_in[2];
    const float* rb   = (const float*)d_in[3];
    const float* W1   = (const float*)d_in[4];
    const float* b1   = (const float*)d_in[5];
    const float* W2   = (const float*)d_in[6];
    const float* b2   = (const float*)d_in[7];
    float* out   = (float*)d_out;
    float* probs = out + (size_t)N_TOK*DIM;

    void *p_xh=nullptr, *p_w1=nullptr, *p_w2=nullptr;
    cudaGetSymbolAddress(&p_xh, g_xh);
    cudaGetSymbolAddress(&p_w1, g_W1h);
    cudaGetSymbolAddress(&p_w2, g_W2h);

    cudaFuncSetAttribute(gemm1_kernel, cudaFuncAttributeMaxDynamicSharedMemorySize, SMEM_G1);
    cudaFuncSetAttribute(gemm2_kernel, cudaFuncAttributeMaxDynamicSharedMemorySize, SMEM_G2);

    // 1: x convert (+counter reset)
    {
        int n4 = N_TOK*DIM/4;
        cvtx_kernel<<<n4/256,256>>>((const float4*)x, (__half*)p_xh, n4);
    }
    // 2: W1+W2 convert
    {
        int n4 = NEXP*DIM*HID/4;
        cvtW_kernel<<<2*n4/256,256>>>((const float4*)W1, (__half*)p_w1,
                                      (const float4*)W2, (__half*)p_w2, n4);
    }
    // 3-5: routing
    router_kernel<<<N_TOK/8,256>>>(x, grad, rW, rb, probs);
    scan_kernel<<<1,32>>>();
    pairs_kernel<<<NPAIR/256,256>>>();
    // 6-7: grouped GEMMs (CTA tile 128x128x64, 2 CTA/SM)
    gemm1_kernel<<<dim3(HID/BN, N_TOK/BM, NEXP),256,SMEM_G1>>>(b1);
    gemm2_kernel<<<dim3(DIM/BN, N_TOK/BM, NEXP),256,SMEM_G2>>>(b2);
    // 8: combine
    combine_kernel<<<(N_TOK*(DIM/4)+255)/256,256>>>(out);
}

// round 16
// speedup vs baseline: 1.2435x; 1.1005x over previous
#include <cuda_runtime.h>
#include <cuda_fp16.h>
#include <math.h>
#include <stdint.h>

// Problem constants
#define N_TOK 16384
#define DIM   1024
#define HID   4096
#define NEXP  8
#define NPAIR (2*N_TOK)
#define PADR  128

// GEMM tiling: CTA 128x128x32, 4 warps (128 thr), warp tile 64x64, 3-stage ring, 2 CTA/SM
#define BM 128
#define BN 128
#define BK 32
#define NSTAGE 3
#define AST 40    // A smem row stride (elems), 80B: 16B-aligned, conflict-free for ldmatrix
#define BST 136   // B smem row stride (elems), 272B: 16B-aligned, conflict-free

#define ABYTES (BM*AST*2)                 // 10240
#define BBYTES (BK*BST*2)                 // 8704
#define STB    (ABYTES + BBYTES)          // 18944 per stage
#define SMEM_G1 (512 + NSTAGE*STB)        // 57344
#define SMEM_G2 (NSTAGE*STB)              // 56832

// ---------------- device scratch (static: no runtime allocation) ----------------
__device__ __half g_xh [(size_t)N_TOK*DIM];
__device__ __half g_W1h[(size_t)NEXP*DIM*HID];
__device__ __half g_W2h[(size_t)NEXP*HID*DIM];
__device__ __half g_H1 [((size_t)NPAIR+PADR)*HID];
__device__ float  g_S  [((size_t)NPAIR+PADR)*DIM];
__device__ int   g_cnt[NEXP];
__device__ int   g_basearr[NEXP];
__device__ int   g_run[NEXP];
__device__ int   g_tok [NPAIR+PADR];
__device__ float g_gate[NPAIR+PADR];
__device__ int   g_prow[NPAIR];
__device__ int   g_tki [NPAIR];
__device__ float g_tkp [NPAIR];

// ---------------- PTX helpers ----------------
static __device__ __forceinline__ uint32_t smem_u32(const void* p){
    return (uint32_t)__cvta_generic_to_shared(p);
}
static __device__ __forceinline__ void cp16(void* s, const void* g){
    asm volatile("cp.async.cg.shared.global [%0],[%1],16;\n" :: "r"(smem_u32(s)), "l"(g));
}
#define CP_COMMIT() asm volatile("cp.async.commit_group;\n")
#define CP_WAIT(n)  asm volatile("cp.async.wait_group %0;\n"::"n"(n))

static __device__ __forceinline__ void ldm4(uint32_t &r0,uint32_t &r1,uint32_t &r2,uint32_t &r3,uint32_t a){
    asm volatile("ldmatrix.sync.aligned.m8n8.x4.shared.b16 {%0,%1,%2,%3},[%4];\n"
                 : "=r"(r0),"=r"(r1),"=r"(r2),"=r"(r3) : "r"(a));
}
static __device__ __forceinline__ void ldm4t(uint32_t &r0,uint32_t &r1,uint32_t &r2,uint32_t &r3,uint32_t a){
    asm volatile("ldmatrix.sync.aligned.m8n8.x4.trans.shared.b16 {%0,%1,%2,%3},[%4];\n"
                 : "=r"(r0),"=r"(r1),"=r"(r2),"=r"(r3) : "r"(a));
}
static __device__ __forceinline__ void mma16816(float* c,
        uint32_t a0,uint32_t a1,uint32_t a2,uint32_t a3, uint32_t b0,uint32_t b1){
    asm volatile("mma.sync.aligned.m16n8k16.row.col.f32.f16.f16.f32 "
        "{%0,%1,%2,%3},{%4,%5,%6,%7},{%8,%9},{%0,%1,%2,%3};\n"
        : "+f"(c[0]),"+f"(c[1]),"+f"(c[2]),"+f"(c[3])
        : "r"(a0),"r"(a1),"r"(a2),"r"(a3),"r"(b0),"r"(b1));
}
static __device__ __forceinline__ float gelu_f(float x){
    return 0.5f*x*(1.0f + erff(x*0.70710678118654752f));
}

// ---------------- conversion kernels (MLP=4: 4 independent loads in flight) ----------------
__global__ void cvtx_kernel(const float4* __restrict__ src, __half* __restrict__ dst, int n4){
    if (blockIdx.x == 0 && threadIdx.x < NEXP) g_cnt[threadIdx.x] = 0;
    int base = blockIdx.x*(blockDim.x*4) + threadIdx.x;
    float4 v[4];
    #pragma unroll
    for (int j=0;j<4;j++){
        int i = base + j*256;
        if (i < n4) v[j] = src[i];
    }
    #pragma unroll
    for (int j=0;j<4;j++){
        int i = base + j*256;
        if (i < n4){
            __half2 h0 = __floats2half2_rn(v[j].x, v[j].y);
            __half2 h1 = __floats2half2_rn(v[j].z, v[j].w);
            ((uint2*)dst)[i] = make_uint2(*(uint32_t*)&h0, *(uint32_t*)&h1);
        }
    }
}
// W1 and W2 in one launch (first n4 quads -> W1, next n4 -> W2); exact multiple sizes.
__global__ void cvtW_kernel(const float4* __restrict__ s1, __half* __restrict__ d1,
                            const float4* __restrict__ s2, __half* __restrict__ d2, int n4){
    int base = blockIdx.x*(blockDim.x*4) + threadIdx.x;
    const float4* s = s1; __half* d = d1;
    if (base >= n4){ s = s2; d = d2; base -= n4; }   // blocks never straddle (n4 % 1024 == 0)
    float4 v[4];
    #pragma unroll
    for (int j=0;j<4;j++) v[j] = s[base + j*256];
    #pragma unroll
    for (int j=0;j<4;j++){
        __half2 h0 = __floats2half2_rn(v[j].x, v[j].y);
        __half2 h1 = __floats2half2_rn(v[j].z, v[j].w);
        ((uint2*)d)[base + j*256] = make_uint2(*(uint32_t*)&h0, *(uint32_t*)&h1);
    }
}

// ---------------- router / scan / pairs ----------------
__global__ __launch_bounds__(256) void router_kernel(
        const float* __restrict__ x, const float* __restrict__ grad,
        const float* __restrict__ rW, const float* __restrict__ rb,
        float* __restrict__ probs){
    __shared__ float sW[DIM*NEXP];
    for (int i = threadIdx.x; i < DIM*NEXP; i += 256) sW[i] = rW[i];
    __syncthreads();
    int warp = threadIdx.x >> 5, lane = threadIdx.x & 31;
    int n = blockIdx.x*8 + warp;
    const float* xr = x + (size_t)n*DIM;
    float a[NEXP];
    #pragma unroll
    for (int e=0;e<NEXP;e++) a[e]=0.f;
    for (int d=lane; d<DIM; d+=32){
        float xv = xr[d];
        #pragma unroll
        for (int e=0;e<NEXP;e++) a[e] += xv * sW[d*NEXP+e];
    }
    #pragma unroll
    for (int off=16; off; off>>=1){
        #pragma unroll
        for (int e=0;e<NEXP;e++) a[e] += __shfl_xor_sync(0xffffffffu, a[e], off);
    }
    float g = grad[n];
    #pragma unroll
    for (int e=0;e<NEXP;e++) a[e] += g*rW[DIM*NEXP+e] + rb[e];
    float mx = a[0];
    #pragma unroll
    for (int e=1;e<NEXP;e++) mx = fmaxf(mx, a[e]);
    float s = 0.f;
    #pragma unroll
    for (int e=0;e<NEXP;e++){ a[e] = expf(a[e]-mx); s += a[e]; }
    float inv = 1.f/s;
    #pragma unroll
    for (int e=0;e<NEXP;e++) a[e] *= inv;
    if (lane < NEXP) probs[(size_t)n*NEXP + lane] = a[lane];
    if (lane == 0){
        int i0 = 0; float p0 = a[0];
        #pragma unroll
        for (int e=1;e<NEXP;e++) if (a[e] > p0){ p0=a[e]; i0=e; }
        int i1 = -1; float p1 = -1.f;
        #pragma unroll
        for (int e=0;e<NEXP;e++) if (e!=i0 && a[e] > p1){ p1=a[e]; i1=e; }
        g_tki[2*n]   = i0; g_tkp[2*n]   = p0;
        g_tki[2*n+1] = i1; g_tkp[2*n+1] = p1;
        atomicAdd(&g_cnt[i0],1);
        atomicAdd(&g_cnt[i1],1);
    }
}

__global__ void scan_kernel(){
    if (threadIdx.x==0){
        int b=0;
        for (int e=0;e<NEXP;e++){ g_basearr[e]=b; g_run[e]=b; b+=g_cnt[e]; }
    }
}

__global__ void pairs_kernel(){
    int p = blockIdx.x*blockDim.x + threadIdx.x;
    if (p >= NPAIR) return;
    int e = g_tki[p];
    int slot = atomicAdd(&g_run[e], 1);
    g_tok[slot]  = p >> 1;
    g_gate[slot] = g_tkp[p];
    g_prow[p]    = slot;
}

// ---------------- GEMM 1: H1[slot,:] = gelu(x[tok[slot]] @ W1[e] + b1[e]) ----------------
// 4 warps, warp tile 64x64, 3-stage cp.async ring.
__global__ __launch_bounds__(128,2) void gemm1_kernel(const float* __restrict__ b1){
    extern __shared__ char smem_raw[];
    int*    tokS = (int*)smem_raw;
    char*   stg  = smem_raw + 512;

    int e   = blockIdx.z;
    int cnt = g_cnt[e];
    int m0  = blockIdx.y*BM;
    if (m0 >= cnt) return;
    int n0    = blockIdx.x*BN;
    int baseE = g_basearr[e];

    int tid = threadIdx.x;
    tokS[tid] = g_tok[baseE + m0 + tid];   // 128 threads == BM; padded array safe past cnt
    __syncthreads();

    const __half* Bg = g_W1h + (size_t)e*DIM*HID;

    int wid = tid>>5, lane = tid&31;
    int wr = (wid>>1)*64, wc = (wid&1)*64;
    float acc[4][8][4];
    #pragma unroll
    for (int i=0;i<4;i++)
        #pragma unroll
        for (int j=0;j<8;j++)
            #pragma unroll
            for (int q=0;q<4;q++) acc[i][j][q]=0.f;

    auto loadStage = [&](int st, int k0){
        __half* Ad = (__half*)(stg + st*STB);
        __half* Bd = (__half*)(stg + st*STB + ABYTES);
        #pragma unroll
        for (int i=0;i<4;i++){                    // A: 128 rows x 32 cols = 512 chunks
            int c = tid + i*128; int r = c>>2, c8 = (c&3)*8;
            cp16(&Ad[r*AST+c8], g_xh + (size_t)tokS[r]*DIM + k0 + c8);
        }
        #pragma unroll
        for (int i=0;i<4;i++){                    // B: 32 rows x 128 cols = 512 chunks
            int c = tid + i*128; int r = c>>4, s8 = (c&15)*8;
            cp16(&Bd[r*BST+s8], Bg + (size_t)(k0+r)*HID + n0 + s8);
        }
    };

    loadStage(0, 0);   CP_COMMIT();
    loadStage(1, BK);  CP_COMMIT();

    const int KT = DIM/BK;   // 32
    for (int kt=0; kt<KT; kt++){
        if (kt < KT-1) { CP_WAIT(1); } else { CP_WAIT(0); }
        __syncthreads();
        if (kt+2 < KT){ loadStage((kt+2)%NSTAGE, (kt+2)*BK); CP_COMMIT(); }

        int st = kt % NSTAGE;
        const __half* Ast = (const __half*)(stg + st*STB);
        const __half* Bst = (const __half*)(stg + st*STB + ABYTES);
        #pragma unroll
        for (int kk=0; kk<BK; kk+=16){
            uint32_t a[4][4];
            #pragma unroll
            for (int mi=0;mi<4;mi++){
                int r  = wr + mi*16 + (lane&15);
                int cb = kk + (lane>>4)*8;
                ldm4(a[mi][0],a[mi][1],a[mi][2],a[mi][3], smem_u32(&Ast[r*AST+cb]));
            }
            uint32_t b[4][4];
            #pragma unroll
            for (int nj=0;nj<4;nj++){
                int r  = kk + (lane&15);
                int cb = wc + nj*16 + (lane>>4)*8;
                ldm4t(b[nj][0],b[nj][1],b[nj][2],b[nj][3], smem_u32(&Bst[r*BST+cb]));
            }
            #pragma unroll
            for (int mi=0;mi<4;mi++)
                #pragma unroll
                for (int ni=0;ni<8;ni++)
                    mma16816(acc[mi][ni], a[mi][0],a[mi][1],a[mi][2],a[mi][3],
                             b[ni>>1][(ni&1)*2], b[ni>>1][(ni&1)*2+1]);
        }
        __syncthreads();
    }

    const float* b1e = b1 + (size_t)e*HID;
    #pragma unroll
    for (int mi=0;mi<4;mi++){
        #pragma unroll
        for (int i=0;i<2;i++){
            int r = wr + mi*16 + (lane>>2) + i*8;
            int m = m0 + r;
            if (m < cnt){
                __half* Hrow = g_H1 + (size_t)(baseE+m)*HID;
                #pragma unroll
                for (int ni=0;ni<8;ni++){
                    int cb = n0 + wc + ni*8 + (lane&3)*2;
                    float v0 = gelu_f(acc[mi][ni][i*2+0] + b1e[cb]);
                    float v1 = gelu_f(acc[mi][ni][i*2+1] + b1e[cb+1]);
                    *((__half2*)(Hrow + cb)) = __floats2half2_rn(v0, v1);
                }
            }
        }
    }
}

// ---------------- GEMM 2: S[slot,:] = gate[slot] * (H1[slot] @ W2[e] + b2[e]) ----------------
__global__ __launch_bounds__(128,2) void gemm2_kernel(const float* __restrict__ b2){
    extern __shared__ char smem_raw[];
    char* stg = smem_raw;

    int e   = blockIdx.z;
    int cnt = g_cnt[e];
    int m0  = blockIdx.y*BM;
    if (m0 >= cnt) return;
    int n0    = blockIdx.x*BN;
    int baseE = g_basearr[e];

    int tid = threadIdx.x;
    const __half* Ag = g_H1  + (size_t)(baseE+m0)*HID;
    const __half* Bg = g_W2h + (size_t)e*HID*DIM;

    int wid = tid>>5, lane = tid&31;
    int wr = (wid>>1)*64, wc = (wid&1)*64;
    float acc[4][8][4];
    #pragma unroll
    for (int i=0;i<4;i++)
        #pragma unroll
        for (int j=0;j<8;j++)
            #pragma unroll
            for (int q=0;q<4;q++) acc[i][j][q]=0.f;

    auto loadStage = [&](int st, int k0){
        __half* Ad = (__half*)(stg + st*STB);
        __half* Bd = (__half*)(stg + st*STB + ABYTES);
        #pragma unroll
        for (int i=0;i<4;i++){
            int c = tid + i*128; int r = c>>2, c8 = (c&3)*8;
            cp16(&Ad[r*AST+c8], Ag + (size_t)r*HID + k0 + c8);
        }
        #pragma unroll
        for (int i=0;i<4;i++){
            int c = tid + i*128; int r = c>>4, s8 = (c&15)*8;
            cp16(&Bd[r*BST+s8], Bg + (size_t)(k0+r)*DIM + n0 + s8);
        }
    };

    loadStage(0, 0);   CP_COMMIT();
    loadStage(1, BK);  CP_COMMIT();

    const int KT = HID/BK;   // 128
    for (int kt=0; kt<KT; kt++){
        if (kt < KT-1) { CP_WAIT(1); } else { CP_WAIT(0); }
        __syncthreads();
        if (kt+2 < KT){ loadStage((kt+2)%NSTAGE, (kt+2)*BK); CP_COMMIT(); }

        int st = kt % NSTAGE;
        const __half* Ast = (const __half*)(stg + st*STB);
        const __half* Bst = (const __half*)(stg + st*STB + ABYTES);
        #pragma unroll
        for (int kk=0; kk<BK; kk+=16){
            uint32_t a[4][4];
            #pragma unroll
            for (int mi=0;mi<4;mi++){
                int r  = wr + mi*16 + (lane&15);
                int cb = kk + (lane>>4)*8;
                ldm4(a[mi][0],a[mi][1],a[mi][2],a[mi][3], smem_u32(&Ast[r*AST+cb]));
            }
            uint32_t b[4][4];
            #pragma unroll
            for (int nj=0;nj<4;nj++){
                int r  = kk + (lane&15);
                int cb = wc + nj*16 + (lane>>4)*8;
                ldm4t(b[nj][0],b[nj][1],b[nj][2],b[nj][3], smem_u32(&Bst[r*BST+cb]));
            }
            #pragma unroll
            for (int mi=0;mi<4;mi++)
                #pragma unroll
                for (int ni=0;ni<8;ni++)
                    mma16816(acc[mi][ni], a[mi][0],a[mi][1],a[mi][2],a[mi][3],
                             b[ni>>1][(ni&1)*2], b[ni>>1][(ni&1)*2+1]);
        }
        __syncthreads();
    }

    const float* b2e = b2 + (size_t)e*DIM;
    #pragma unroll
    for (int mi=0;mi<4;mi++){
        #pragma unroll
        for (int i=0;i<2;i++){
            int r = wr + mi*16 + (lane>>2) + i*8;
            int m = m0 + r;
            if (m < cnt){
                int slot = baseE + m;
                float gate = g_gate[slot];
                float* Srow = g_S + (size_t)slot*DIM;
                #pragma unroll
                for (int ni=0;ni<8;ni++){
                    int cb = n0 + wc + ni*8 + (lane&3)*2;
                    float v0 = gate*(acc[mi][ni][i*2+0] + b2e[cb]);
                    float v1 = gate*(acc[mi][ni][i*2+1] + b2e[cb+1]);
                    *((float2*)(Srow + cb)) = make_float2(v0, v1);
                }
            }
        }
    }
}

// ---------------- combine: out[n] = S[prow[2n]] + S[prow[2n+1]] ----------------
__global__ void combine_kernel(float* __restrict__ out){
    int t = blockIdx.x*blockDim.x + threadIdx.x;   // over N_TOK*DIM/4
    if (t >= N_TOK*(DIM/4)) return;
    int n  = t >> 8;        // DIM/4 = 256
    int c4 = t & 255;
    int p0 = g_prow[2*n], p1 = g_prow[2*n+1];
    const float4* s0 = (const float4*)(g_S + (size_t)p0*DIM);
    const float4* s1 = (const float4*)(g_S + (size_t)p1*DIM);
    float4 v0 = s0[c4], v1 = s1[c4];
    float4 r;
    r.x = v0.x+v1.x; r.y = v0.y+v1.y; r.z = v0.z+v1.z; r.w = v0.w+v1.w;
    ((float4*)out)[t] = r;
}

// ---------------- launch ----------------
extern "C" void kernel_launch(void* const* d_in, const int* in_sizes, int n_in,
                              void* d_out, int out_size){
    (void)in_sizes; (void)n_in; (void)out_size;
    const float* x    = (const float*)d_in[0];
    const float* grad = (const float*)d_in[1];
    const float* rW   = (const float*)d_in[2];
    const float* rb   = (const float*)d_in[3];
    const float* W1   = (const float*)d_in[4];
    const float* b1   = (const float*)d_in[5];
    const float* W2   = (const float*)d_in[6];
    const float* b2   = (const float*)d_in[7];
    float* out   = (float*)d_out;
    float* probs = out + (size_t)N_TOK*DIM;

    void *p_xh=nullptr, *p_w1=nullptr, *p_w2=nullptr;
    cudaGetSymbolAddress(&p_xh, g_xh);
    cudaGetSymbolAddress(&p_w1, g_W1h);
    cudaGetSymbolAddress(&p_w2, g_W2h);

    cudaFuncSetAttribute(gemm1_kernel, cudaFuncAttributeMaxDynamicSharedMemorySize, SMEM_G1);
    cudaFuncSetAttribute(gemm2_kernel, cudaFuncAttributeMaxDynamicSharedMemorySize, SMEM_G2);

    // 1: x convert (+counter reset), MLP=4
    {
        int n4 = N_TOK*DIM/4;                      // 4194304, divisible by 1024
        cvtx_kernel<<<n4/1024,256>>>((const float4*)x, (__half*)p_xh, n4);
    }
    // 2: W1+W2 convert, MLP=4
    {
        int n4 = NEXP*DIM*HID/4;                   // 8388608, divisible by 1024
        cvtW_kernel<<<2*n4/1024,256>>>((const float4*)W1, (__half*)p_w1,
                                       (const float4*)W2, (__half*)p_w2, n4);
    }
    // 3-5: routing
    router_kernel<<<N_TOK/8,256>>>(x, grad, rW, rb, probs);
    scan_kernel<<<1,32>>>();
    pairs_kernel<<<NPAIR/256,256>>>();
    // 6-7: grouped GEMMs (CTA 128x128x32, 4 warps, warp tile 64x64, 2 CTA/SM)
    gemm1_kernel<<<dim3(HID/BN, N_TOK/BM, NEXP),128,SMEM_G1>>>(b1);
    gemm2_kernel<<<dim3(DIM/BN, N_TOK/BM, NEXP),128,SMEM_G2>>>(b2);
    // 8: combine
    combine_kernel<<<(N_TOK*(DIM/4)+255)/256,256>>>(out);
}